// round 1
// baseline (speedup 1.0000x reference)
#include <cuda_runtime.h>
#include <cstdint>

#define BATCH 128
#define NNODE 64
#define NF    64
#define C1    256   // fe hidden
#define C2    96    // fe out
#define CN1   256   // fn hidden
#define CN2   64    // fn out

// ---------------- scratch (device globals: no allocations allowed) ----------
__device__ float g_P[BATCH * NNODE * C1];   // x_i @ W0[0:64] + b0
__device__ float g_Q[BATCH * NNODE * C1];   // x_j @ W0[64:128]

__device__ __forceinline__ float lrelu(float v) { return v > 0.f ? v : 0.2f * v; }

#define CP_ASYNC16(smaddr, gptr) \
    asm volatile("cp.async.cg.shared.global [%0], [%1], 16;" :: "r"(smaddr), "l"(gptr))
#define CP_COMMIT() asm volatile("cp.async.commit_group;")
#define CP_WAIT1()  asm volatile("cp.async.wait_group 1;" ::: "memory")
#define CP_WAIT0()  asm volatile("cp.async.wait_group 0;" ::: "memory")

#define PACK2(dst, fv) \
    asm("mov.b64 %0, {%1, %1};" : "=l"(dst) : "r"(__float_as_uint(fv)))
#define FMA2(acc, a, b) \
    asm("fma.rn.f32x2 %0, %1, %2, %0;" : "+l"(acc) : "l"(a), "l"(b))

// ---------------- kernel 1: P/Q precompute -----------------------------------
__global__ __launch_bounds__(256) void pq_kernel(
    const float* __restrict__ x, const float* __restrict__ W0,
    const float* __restrict__ b0)
{
    __shared__ float xs[16 * 64];
    const int r0 = blockIdx.x * 16;         // 8192 rows / 16 = 512 blocks
    const int tid = threadIdx.x;

    ((float4*)xs)[tid] = ((const float4*)(x + (size_t)r0 * 64))[tid];
    __syncthreads();

    const int c = tid;
    float accP[16], accQ[16];
#pragma unroll
    for (int r = 0; r < 16; r++) { accP[r] = 0.f; accQ[r] = 0.f; }

#pragma unroll 4
    for (int f = 0; f < 64; f++) {
        float wp = W0[f * C1 + c];
        float wq = W0[(64 + f) * C1 + c];
#pragma unroll
        for (int r = 0; r < 16; r++) {
            float xv = xs[r * 64 + f];
            accP[r] = fmaf(xv, wp, accP[r]);
            accQ[r] = fmaf(xv, wq, accQ[r]);
        }
    }
    float bias = b0[c];
#pragma unroll
    for (int r = 0; r < 16; r++) {
        g_P[(size_t)(r0 + r) * C1 + c] = accP[r] + bias;
        g_Q[(size_t)(r0 + r) * C1 + c] = accQ[r];
    }
}

// ---------------- main fused kernel ------------------------------------------
// smem layout (bytes)
#define SM_H0   0        // 64*256*4 = 65536
#define SM_H1   65536    // 65536
#define SM_WB   131072   // 2 * 16384 weight double buffer
#define SM_XS   163840   // 64*64*4 = 16384
#define SM_PV   180224   // 1024
#define SM_W0D  181248   // 1024
#define SM_DIST 182272   // 256
#define SM_RED  182528   // 6144
#define SM_AGG  188672   // 384
#define SM_Z    189056   // 1024
#define SMEM_BYTES 190080

__global__ void __launch_bounds__(256, 1) mp_main(
    const float* __restrict__ x,
    const float* __restrict__ W0,
    const float* __restrict__ W1, const float* __restrict__ b1,
    const float* __restrict__ W2, const float* __restrict__ b2,
    const float* __restrict__ Wn0, const float* __restrict__ bn0,
    const float* __restrict__ Wn1, const float* __restrict__ bn1,
    float* __restrict__ out)
{
    extern __shared__ char sm[];
    float* h0s  = (float*)(sm + SM_H0);
    float* h1s  = (float*)(sm + SM_H1);
    float* wb   = (float*)(sm + SM_WB);
    float* xs   = (float*)(sm + SM_XS);
    float* pv   = (float*)(sm + SM_PV);
    float* w0d  = (float*)(sm + SM_W0D);
    float* dist = (float*)(sm + SM_DIST);
    float* red  = (float*)(sm + SM_RED);
    float* agg  = (float*)(sm + SM_AGG);
    float* z    = (float*)(sm + SM_Z);

    const int tid = threadIdx.x;
    const int b = blockIdx.x >> 6;
    const int i = blockIdx.x & 63;

    // -- stage inputs -------------------------------------------------------
    {
        const float4* xin = (const float4*)(x + (size_t)b * NNODE * NF);
        float4* xd = (float4*)xs;
#pragma unroll
        for (int t = 0; t < 4; t++) xd[tid + t * 256] = xin[tid + t * 256];
        pv[tid]  = g_P[(size_t)(b * 64 + i) * C1 + tid];
        w0d[tid] = W0[128 * C1 + tid];
    }
    __syncthreads();

    // -- distances ----------------------------------------------------------
    if (tid < 64) {
        const float* xi = xs + i * 64;
        const float* xj = xs + tid * 64;
        float s = 0.f;
#pragma unroll
        for (int f = 0; f < 64; f++) {
            float d = xj[f] - xi[f] + 1e-12f;
            s = fmaf(d, d, s);
        }
        dist[tid] = sqrtf(s);
    }
    __syncthreads();

    // -- h0 = lrelu(P_i + Q_j + dist*w0d) -----------------------------------
    {
        const float* Qb = g_Q + (size_t)(b * 64) * C1;
        float pc = pv[tid], wc = w0d[tid];
#pragma unroll 8
        for (int j = 0; j < 64; j++) {
            float v = pc + Qb[(size_t)j * C1 + tid] + dist[j] * wc;
            h0s[j * C1 + tid] = lrelu(v);
        }
    }
    __syncthreads();

    // -- GEMM1: h1 = lrelu(h0[64x256] @ W1[256x256] + b1) -------------------
    const int ct = tid & 31;   // c block: ct*8
    const int jt = tid >> 5;   // j block: jt*8
    {
        auto loadW1 = [&](int buf, int k0) {
            unsigned sb = (unsigned)__cvta_generic_to_shared(wb + buf * 4096);
            const float4* g = (const float4*)(W1 + (size_t)k0 * C1);
#pragma unroll
            for (int t = 0; t < 4; t++)
                CP_ASYNC16(sb + (tid + t * 256) * 16, (const void*)(g + tid + t * 256));
            CP_COMMIT();
        };

        unsigned long long acc[32];
#pragma unroll
        for (int r = 0; r < 32; r++) acc[r] = 0ull;

        loadW1(0, 0);
        for (int t = 0; t < 16; t++) {
            if (t < 15) { loadW1((t + 1) & 1, (t + 1) * 16); CP_WAIT1(); }
            else        { CP_WAIT0(); }
            __syncthreads();
            const float* A  = h0s + (jt * 8) * C1 + t * 16;
            const float* Bt = wb + (t & 1) * 4096;       // [16][256]
#pragma unroll
            for (int kk = 0; kk < 16; kk++) {
                unsigned long long ap[8];
#pragma unroll
                for (int r = 0; r < 8; r++) PACK2(ap[r], A[r * C1 + kk]);
                const unsigned long long* Bq =
                    (const unsigned long long*)(Bt + kk * C1 + ct * 8);
                unsigned long long bp[4];
#pragma unroll
                for (int e = 0; e < 4; e++) bp[e] = Bq[e];
#pragma unroll
                for (int r = 0; r < 8; r++)
#pragma unroll
                    for (int e = 0; e < 4; e++) FMA2(acc[r * 4 + e], ap[r], bp[e]);
            }
            __syncthreads();
        }
        // epilogue: bias + lrelu -> h1 smem
#pragma unroll
        for (int e = 0; e < 4; e++) {
            int c0 = ct * 8 + 2 * e;
            float bb0 = b1[c0], bb1 = b1[c0 + 1];
#pragma unroll
            for (int r = 0; r < 8; r++) {
                unsigned long long v = acc[r * 4 + e];
                float lo = lrelu(__uint_as_float((unsigned)v) + bb0);
                float hi = lrelu(__uint_as_float((unsigned)(v >> 32)) + bb1);
                int row = jt * 8 + r;
                h1s[row * C1 + c0]     = lo;
                h1s[row * C1 + c0 + 1] = hi;
            }
        }
    }
    __syncthreads();

    // -- GEMM2: h2 = lrelu(h1[64x256] @ W2[256x96] + b2), then sum over j ---
    const int ct2 = tid & 15;  // c block: ct2*6
    const int jt2 = tid >> 4;  // j block: jt2*4
    {
        auto loadW2 = [&](int buf, int k0) {  // 32x96 floats = 768 float4
            unsigned sb = (unsigned)__cvta_generic_to_shared(wb + buf * 4096);
            const float4* g = (const float4*)(W2 + (size_t)k0 * C2);
#pragma unroll
            for (int t = 0; t < 3; t++)
                CP_ASYNC16(sb + (tid + t * 256) * 16, (const void*)(g + tid + t * 256));
            CP_COMMIT();
        };

        unsigned long long acc2[12];
#pragma unroll
        for (int r = 0; r < 12; r++) acc2[r] = 0ull;

        loadW2(0, 0);
        for (int t = 0; t < 8; t++) {
            if (t < 7) { loadW2((t + 1) & 1, (t + 1) * 32); CP_WAIT1(); }
            else       { CP_WAIT0(); }
            __syncthreads();
            const float* A  = h1s + (jt2 * 4) * C1 + t * 32;
            const float* Bt = wb + (t & 1) * 4096;      // [32][96]
#pragma unroll
            for (int kk = 0; kk < 32; kk++) {
                unsigned long long ap[4];
#pragma unroll
                for (int r = 0; r < 4; r++) PACK2(ap[r], A[r * C1 + kk]);
                const unsigned long long* Bq =
                    (const unsigned long long*)(Bt + kk * C2 + ct2 * 6);
                unsigned long long bp[3];
#pragma unroll
                for (int e = 0; e < 3; e++) bp[e] = Bq[e];
#pragma unroll
                for (int r = 0; r < 4; r++)
#pragma unroll
                    for (int e = 0; e < 3; e++) FMA2(acc2[r * 3 + e], ap[r], bp[e]);
            }
            __syncthreads();
        }
        // epilogue: bias + lrelu, partial row-sum over this thread's 4 rows
        float ps[6];
#pragma unroll
        for (int cc = 0; cc < 6; cc++) ps[cc] = 0.f;
#pragma unroll
        for (int e = 0; e < 3; e++) {
            int c0 = ct2 * 6 + 2 * e;
            float bb0 = b2[c0], bb1 = b2[c0 + 1];
#pragma unroll
            for (int r = 0; r < 4; r++) {
                unsigned long long v = acc2[r * 3 + e];
                ps[2 * e]     += lrelu(__uint_as_float((unsigned)v) + bb0);
                ps[2 * e + 1] += lrelu(__uint_as_float((unsigned)(v >> 32)) + bb1);
            }
        }
#pragma unroll
        for (int cc = 0; cc < 6; cc++) red[jt2 * 96 + ct2 * 6 + cc] = ps[cc];
    }
    __syncthreads();

    if (tid < 96) {
        float s = 0.f;
#pragma unroll
        for (int w = 0; w < 16; w++) s += red[w * 96 + tid];
        agg[tid] = s;
    }
    __syncthreads();

    // -- node MLP -----------------------------------------------------------
    float* t160 = red;                 // reuse (first 160 floats)
    if (tid < 160) t160[tid] = (tid < 96) ? agg[tid] : xs[i * 64 + (tid - 96)];
    __syncthreads();
    {
        float a = bn0[tid];
#pragma unroll 8
        for (int k = 0; k < 160; k++)
            a = fmaf(t160[k], Wn0[(size_t)k * CN1 + tid], a);
        z[tid] = lrelu(a);
    }
    __syncthreads();
    float* part = red + 256;           // 256 floats of partials
    {
        int q = tid >> 6, c = tid & 63;
        float a = 0.f;
#pragma unroll 8
        for (int k = 0; k < 64; k++)
            a = fmaf(z[q * 64 + k], Wn1[(size_t)(q * 64 + k) * CN2 + c], a);
        part[q * 64 + c] = a;
    }
    __syncthreads();
    if (tid < 64) {
        float a = bn1[tid] + part[tid] + part[64 + tid] + part[128 + tid] + part[192 + tid];
        out[(size_t)blockIdx.x * CN2 + tid] = a;
    }
}

// ---------------- launch -----------------------------------------------------
extern "C" void kernel_launch(void* const* d_in, const int* in_sizes, int n_in,
                              void* d_out, int out_size)
{
    const float* x    = (const float*)d_in[0];
    const float* feW0 = (const float*)d_in[1];
    const float* feb0 = (const float*)d_in[2];
    const float* feW1 = (const float*)d_in[3];
    const float* feb1 = (const float*)d_in[4];
    const float* feW2 = (const float*)d_in[5];
    const float* feb2 = (const float*)d_in[6];
    const float* fnW0 = (const float*)d_in[7];
    const float* fnb0 = (const float*)d_in[8];
    const float* fnW1 = (const float*)d_in[9];
    const float* fnb1 = (const float*)d_in[10];
    float* out = (float*)d_out;

    cudaFuncSetAttribute(mp_main, cudaFuncAttributeMaxDynamicSharedMemorySize,
                         SMEM_BYTES);

    pq_kernel<<<512, 256>>>(x, feW0, feb0);
    mp_main<<<BATCH * NNODE, 256, SMEM_BYTES>>>(
        x, feW0, feW1, feb1, feW2, feb2, fnW0, fnb0, fnW1, fnb1, out);
}